// round 1
// baseline (speedup 1.0000x reference)
#include <cuda_runtime.h>
#include <math.h>

#define BATCH 8192
#define INDIM 512
#define EMB   64
#define KC    256
#define DENSE 1152

// ---------------- scratch (static __device__ globals; no runtime allocs) ----
__device__ float g_h1[BATCH * DENSE];
__device__ float g_h2[BATCH * DENSE];
__device__ float g_enc[BATCH * EMB];
__device__ float g_sample[BATCH * EMB];
__device__ float g_M[KC * EMB * EMB];      // L^{-1} (lower-tri, upper zeroed)
__device__ float g_Lraw[KC * EMB * EMB];   // chol(cov) no jitter (upper zeroed)
__device__ float g_t[KC * EMB];            // M * mu
__device__ float g_c[KC];                  // log(size) - 0.5*D*log2pi - sum(log diag L)
__device__ int   g_idx[BATCH];

__device__ __forceinline__ float selu_f(float x) {
    const float alpha = 1.6732632423543772f;
    const float scale = 1.0507009873554805f;
    return scale * (x > 0.f ? x : alpha * expm1f(x));
}

// ---------------- cluster prep: cholesky, inverse, logdet, raw cholesky -----
__device__ void chol64(float (*A)[EMB + 1], float (*L)[EMB + 1], int tid) {
    __shared__ float sdiag;
    for (int j = 0; j < EMB; j++) {
        if (tid == j) {
            float s = A[j][j];
            for (int q = 0; q < j; q++) s -= L[j][q] * L[j][q];
            float d = sqrtf(fmaxf(s, 1e-30f));
            L[j][j] = d;
            sdiag = d;
        }
        __syncthreads();
        if (tid > j) {
            float s = A[tid][j];
            for (int q = 0; q < j; q++) s -= L[tid][q] * L[j][q];
            L[tid][j] = s / sdiag;
        }
        __syncthreads();
    }
}

__global__ void prep_clusters(const float* __restrict__ cov,
                              const float* __restrict__ means,
                              const float* __restrict__ sizes) {
    __shared__ float sA[EMB][EMB + 1];
    __shared__ float sL[EMB][EMB + 1];
    __shared__ float smu[EMB];
    const int k = blockIdx.x;
    const int tid = threadIdx.x;  // 64 threads
    const float* Ck = cov + (long)k * EMB * EMB;

    // ---- jittered cholesky ----
    for (int i = 0; i < EMB; i++) { sA[i][tid] = Ck[i * EMB + tid]; sL[i][tid] = 0.f; }
    __syncthreads();
    sA[tid][tid] += 0.005f;
    __syncthreads();
    chol64(sA, sL, tid);

    if (tid == 0) {
        float ld = 0.f;
        for (int j = 0; j < EMB; j++) ld += logf(sL[j][j]);
        // log(size) - 0.5*(D*log(2pi) + 2*sum(log diag))
        g_c[k] = logf(sizes[k]) - 0.5f * (EMB * 1.8378770664093453f) - ld;
    }

    // ---- invert L (lower triangular): sA := L^{-1}, one column per thread ----
    for (int i = 0; i < EMB; i++) sA[i][tid] = 0.f;
    __syncthreads();
    {
        const int c = tid;
        for (int i = c; i < EMB; i++) {
            float s = (i == c) ? 1.f : 0.f;
            for (int q = c; q < i; q++) s -= sL[i][q] * sA[q][c];
            sA[i][c] = s / sL[i][i];
        }
    }
    __syncthreads();
    for (int r = 0; r < EMB; r++)
        g_M[(long)k * EMB * EMB + r * EMB + tid] = sA[r][tid];
    smu[tid] = means[k * EMB + tid];
    __syncthreads();
    {
        float s = 0.f;
        for (int j = 0; j < EMB; j++) s += sA[tid][j] * smu[j];
        g_t[k * EMB + tid] = s;
    }
    __syncthreads();

    // ---- raw cholesky (no jitter) for sampling ----
    for (int i = 0; i < EMB; i++) { sA[i][tid] = Ck[i * EMB + tid]; sL[i][tid] = 0.f; }
    __syncthreads();
    chol64(sA, sL, tid);
    for (int r = 0; r < EMB; r++)
        g_Lraw[(long)k * EMB * EMB + r * EMB + tid] = sL[r][tid];
}

// ---------------- fp32 SGEMM: C[M,N] = act(A[M,Kd] @ W[N,Kd]^T + bias) ------
template <int BN, int ACT>
__global__ __launch_bounds__(256) void sgemm(const float* __restrict__ A,
                                             const float* __restrict__ W,
                                             const float* __restrict__ bias,
                                             float* __restrict__ C,
                                             int M, int N, int Kd) {
    const int BM = 128, BK = 16;
    const int TN = BN / 16;  // per-thread cols: 8 (BN=128) or 4 (BN=64)
    __shared__ float As[BM][BK + 1];
    __shared__ float Ws[BN][BK + 1];
    const int tid = threadIdx.x;
    const int tx = tid & 15, ty = tid >> 4;
    const int m0 = blockIdx.y * BM, n0 = blockIdx.x * BN;

    float acc[8][TN];
#pragma unroll
    for (int i = 0; i < 8; i++)
#pragma unroll
        for (int j = 0; j < TN; j++) acc[i][j] = 0.f;

    for (int k0 = 0; k0 < Kd; k0 += BK) {
        // A tile: 128x16 = 512 float4, 2 per thread
#pragma unroll
        for (int q = 0; q < 2; q++) {
            int f = tid + q * 256;
            int r = f >> 2, c = (f & 3) * 4;
            float4 v = *reinterpret_cast<const float4*>(A + (long)(m0 + r) * Kd + k0 + c);
            As[r][c] = v.x; As[r][c + 1] = v.y; As[r][c + 2] = v.z; As[r][c + 3] = v.w;
        }
        // W tile: BNx16
#pragma unroll
        for (int q = 0; q < (BN * BK) / 1024; q++) {
            int f = tid + q * 256;
            int r = f >> 2, c = (f & 3) * 4;
            float4 v = *reinterpret_cast<const float4*>(W + (long)(n0 + r) * Kd + k0 + c);
            Ws[r][c] = v.x; Ws[r][c + 1] = v.y; Ws[r][c + 2] = v.z; Ws[r][c + 3] = v.w;
        }
        __syncthreads();
#pragma unroll
        for (int kk = 0; kk < BK; kk++) {
            float a[8], b[TN];
#pragma unroll
            for (int i = 0; i < 8; i++) a[i] = As[ty * 8 + i][kk];
#pragma unroll
            for (int j = 0; j < TN; j++) b[j] = Ws[tx * TN + j][kk];
#pragma unroll
            for (int i = 0; i < 8; i++)
#pragma unroll
                for (int j = 0; j < TN; j++) acc[i][j] = fmaf(a[i], b[j], acc[i][j]);
        }
        __syncthreads();
    }

#pragma unroll
    for (int i = 0; i < 8; i++) {
        const int m = m0 + ty * 8 + i;
#pragma unroll
        for (int j = 0; j < TN; j++) {
            const int n = n0 + tx * TN + j;
            float v = acc[i][j] + bias[n];
            if (ACT) v = selu_f(v);
            C[(long)m * N + n] = v;
        }
    }
}

// ---------------- log_probs + argmax: lp[b,k] = c_k - 0.5*|M_k enc_b - t_k|^2
__global__ __launch_bounds__(256) void logprob_kernel(float* __restrict__ out_lp,
                                                      float* __restrict__ out_idx) {
    __shared__ float sM[EMB][EMB + 4];  // stride 68 floats -> 16B-aligned rows
    __shared__ float sE[EMB][EMB + 1];
    __shared__ float sT[EMB];
    __shared__ float sP[64][4];
    const int tid = threadIdx.x;           // 256 = 64 b-rows x 4 groups
    const int b0 = blockIdx.x * 64;
    const int b = tid >> 2, g = tid & 3;

    // stage enc tile, then cache this thread's row in registers
    for (int e = tid; e < 64 * EMB; e += 256) {
        int r = e >> 6, c = e & 63;
        sE[r][c] = g_enc[(long)(b0 + r) * EMB + c];
    }
    __syncthreads();
    float ereg[EMB];
#pragma unroll
    for (int kk = 0; kk < EMB; kk++) ereg[kk] = sE[b][kk];

    float best = -3.4e38f;
    int bestk = 0;
    for (int k = 0; k < KC; k++) {
        __syncthreads();  // (A) prev-iter sP reads done before reload
        for (int e = tid; e < EMB * EMB; e += 256) {
            int r = e >> 6, c = e & 63;
            sM[r][c] = g_M[(long)k * EMB * EMB + e];
        }
        if (tid < EMB) sT[tid] = g_t[k * EMB + tid];
        __syncthreads();  // (B) tiles ready

        float q = 0.f;
#pragma unroll
        for (int ii = 0; ii < 16; ii++) {
            const int i = ii * 4 + g;  // 4 groups hit 4 distinct banks-groups
            float z = -sT[i];
#pragma unroll
            for (int k4 = 0; k4 < 16; k4++) {
                float4 m = *reinterpret_cast<const float4*>(&sM[i][k4 * 4]);
                z += m.x * ereg[k4 * 4 + 0] + m.y * ereg[k4 * 4 + 1] +
                     m.z * ereg[k4 * 4 + 2] + m.w * ereg[k4 * 4 + 3];
            }
            q += z * z;
        }
        sP[b][g] = q;
        __syncthreads();  // (C) partials ready

        if (g == 0) {
            float quad = sP[b][0] + sP[b][1] + sP[b][2] + sP[b][3];
            float lp = g_c[k] - 0.5f * quad;
            out_lp[(long)(b0 + b) * KC + k] = lp;
            if (lp > best) { best = lp; bestk = k; }  // strict > : first max wins
        }
    }
    if (g == 0) {
        g_idx[b0 + b] = bestk;
        out_idx[b0 + b] = (float)bestk;
    }
}

// ---------------- sample = means[idx] + L_raw[idx] @ noise -------------------
__global__ void sample_kernel(const float* __restrict__ means,
                              const float* __restrict__ noise) {
    __shared__ float sn[EMB];
    const int bb = blockIdx.x;
    const int i = threadIdx.x;  // 64
    sn[i] = noise[(long)bb * EMB + i];
    __syncthreads();
    const int k = g_idx[bb];
    const float* Lr = g_Lraw + (long)k * EMB * EMB + i * EMB;
    float s = means[k * EMB + i];
    for (int j = 0; j <= i; j++) s = fmaf(Lr[j], sn[j], s);
    g_sample[(long)bb * EMB + i] = s;
}

// ---------------- launch ----------------------------------------------------
extern "C" void kernel_launch(void* const* d_in, const int* in_sizes, int n_in,
                              void* d_out, int out_size) {
    const float* x     = (const float*)d_in[0];
    const float* noise = (const float*)d_in[1];
    const float* eW1 = (const float*)d_in[2];  const float* eb1 = (const float*)d_in[3];
    const float* eW2 = (const float*)d_in[4];  const float* eb2 = (const float*)d_in[5];
    const float* eW3 = (const float*)d_in[6];  const float* eb3 = (const float*)d_in[7];
    const float* dW1 = (const float*)d_in[8];  const float* db1 = (const float*)d_in[9];
    const float* dW2 = (const float*)d_in[10]; const float* db2 = (const float*)d_in[11];
    const float* dW3 = (const float*)d_in[12]; const float* db3 = (const float*)d_in[13];
    const float* means = (const float*)d_in[14];
    const float* sizes = (const float*)d_in[15];
    const float* cov   = (const float*)d_in[16];

    float* out = (float*)d_out;
    float* out_dec = out;                                   // [B, INDIM]
    float* out_lp  = out + (long)BATCH * INDIM;             // [B, KC]
    float* out_idx = out + (long)BATCH * (INDIM + KC);      // [B] as float

    float *h1, *h2, *enc, *smp;
    cudaGetSymbolAddress((void**)&h1, g_h1);
    cudaGetSymbolAddress((void**)&h2, g_h2);
    cudaGetSymbolAddress((void**)&enc, g_enc);
    cudaGetSymbolAddress((void**)&smp, g_sample);

    // cluster prep (cholesky / inverse / logdet / raw cholesky)
    prep_clusters<<<KC, EMB>>>(cov, means, sizes);

    // encoder
    sgemm<128, 1><<<dim3(DENSE / 128, BATCH / 128), 256>>>(x,  eW1, eb1, h1, BATCH, DENSE, INDIM);
    sgemm<128, 1><<<dim3(DENSE / 128, BATCH / 128), 256>>>(h1, eW2, eb2, h2, BATCH, DENSE, DENSE);
    sgemm<64, 0><<<dim3(EMB / 64, BATCH / 128), 256>>>(h2, eW3, eb3, enc, BATCH, EMB, DENSE);

    // quantize
    logprob_kernel<<<BATCH / 64, 256>>>(out_lp, out_idx);
    sample_kernel<<<BATCH, EMB>>>(means, noise);

    // decoder (input is exactly `sample` -- straight-through estimator)
    sgemm<128, 1><<<dim3(DENSE / 128, BATCH / 128), 256>>>(smp, dW1, db1, h1, BATCH, DENSE, EMB);
    sgemm<128, 1><<<dim3(DENSE / 128, BATCH / 128), 256>>>(h1,  dW2, db2, h2, BATCH, DENSE, DENSE);
    sgemm<128, 0><<<dim3(INDIM / 128, BATCH / 128), 256>>>(h2, dW3, db3, out_dec, BATCH, INDIM, DENSE);
}

// round 3
// speedup vs baseline: 1.9497x; 1.9497x over previous
#include <cuda_runtime.h>
#include <math.h>
#include <stdint.h>

#define BATCH 8192
#define INDIM 512
#define EMB   64
#define KC    256
#define DENSE 1152

// ---------------- scratch globals -------------------------------------------
__device__ float g_h1[BATCH * DENSE];
__device__ float g_h2[BATCH * DENSE];
__device__ float g_enc[BATCH * EMB];
__device__ float g_sample[BATCH * EMB];
__device__ float g_M[KC * EMB * EMB];      // L^{-1} (lower-tri)
__device__ float g_Lraw[KC * EMB * EMB];   // chol(cov) no jitter
__device__ float g_t[KC * EMB];            // M * mu
__device__ float g_c[KC];                  // log(size) - 0.5*D*log2pi - sum log diag
__device__ float g_lpT[KC * BATCH];        // log_probs transposed [K][B]
__device__ int   g_idx[BATCH];

__device__ __forceinline__ float selu_f(float x) {
    const float alpha = 1.6732632423543772f;
    const float scale = 1.0507009873554805f;
    return scale * (x > 0.f ? x : alpha * expm1f(x));
}

// ---------------- ptx helpers ----------------------------------------------
__device__ __forceinline__ void cpa16(void* d, const void* s) {
    uint32_t a = (uint32_t)__cvta_generic_to_shared(d);
    asm volatile("cp.async.cg.shared.global [%0],[%1],16;" :: "r"(a), "l"(s));
}
__device__ __forceinline__ void cp_commit() { asm volatile("cp.async.commit_group;"); }
template <int N> __device__ __forceinline__ void cp_wait() {
    asm volatile("cp.async.wait_group %0;" :: "n"(N));
}
__device__ __forceinline__ void split_tf32(float v, uint32_t& hi, uint32_t& lo) {
    uint32_t h; asm("cvt.rna.tf32.f32 %0,%1;" : "=r"(h) : "f"(v));
    float r = v - __uint_as_float(h);
    uint32_t l; asm("cvt.rna.tf32.f32 %0,%1;" : "=r"(l) : "f"(r));
    hi = h; lo = l;
}
__device__ __forceinline__ void mma8(float* c, const uint32_t* a, const uint32_t* b) {
    asm volatile(
        "mma.sync.aligned.m16n8k8.row.col.f32.tf32.tf32.f32 "
        "{%0,%1,%2,%3},{%4,%5,%6,%7},{%8,%9},{%0,%1,%2,%3};"
        : "+f"(c[0]), "+f"(c[1]), "+f"(c[2]), "+f"(c[3])
        : "r"(a[0]), "r"(a[1]), "r"(a[2]), "r"(a[3]), "r"(b[0]), "r"(b[1]));
}

// ---------------- cluster prep ----------------------------------------------
__device__ void chol64(float (*A)[EMB + 1], float (*L)[EMB + 1], int tid) {
    __shared__ float sdiag;
    for (int j = 0; j < EMB; j++) {
        if (tid == j) {
            float s = A[j][j];
            for (int q = 0; q < j; q++) s -= L[j][q] * L[j][q];
            float d = sqrtf(fmaxf(s, 1e-30f));
            L[j][j] = d; sdiag = d;
        }
        __syncthreads();
        if (tid > j) {
            float s = A[tid][j];
            for (int q = 0; q < j; q++) s -= L[tid][q] * L[j][q];
            L[tid][j] = s / sdiag;
        }
        __syncthreads();
    }
}

__global__ void prep_clusters(const float* __restrict__ cov,
                              const float* __restrict__ means,
                              const float* __restrict__ sizes) {
    __shared__ float sA[EMB][EMB + 1];
    __shared__ float sL[EMB][EMB + 1];
    __shared__ float smu[EMB];
    const int k = blockIdx.x;
    const int tid = threadIdx.x;
    const float* Ck = cov + (size_t)k * EMB * EMB;

    for (int i = 0; i < EMB; i++) { sA[i][tid] = Ck[i * EMB + tid]; sL[i][tid] = 0.f; }
    __syncthreads();
    sA[tid][tid] += 0.005f;
    __syncthreads();
    chol64(sA, sL, tid);

    if (tid == 0) {
        float ld = 0.f;
        for (int j = 0; j < EMB; j++) ld += logf(sL[j][j]);
        g_c[k] = logf(sizes[k]) - 0.5f * (EMB * 1.8378770664093453f) - ld;
    }

    for (int i = 0; i < EMB; i++) sA[i][tid] = 0.f;
    __syncthreads();
    {
        const int c = tid;
        for (int i = c; i < EMB; i++) {
            float s = (i == c) ? 1.f : 0.f;
            for (int q = c; q < i; q++) s -= sL[i][q] * sA[q][c];
            sA[i][c] = s / sL[i][i];
        }
    }
    __syncthreads();
    for (int r = 0; r < EMB; r++)
        g_M[(size_t)k * EMB * EMB + r * EMB + tid] = sA[r][tid];
    smu[tid] = means[k * EMB + tid];
    __syncthreads();
    {
        float s = 0.f;
        for (int j = 0; j < EMB; j++) s += sA[tid][j] * smu[j];
        g_t[k * EMB + tid] = s;
    }
    __syncthreads();

    for (int i = 0; i < EMB; i++) { sA[i][tid] = Ck[i * EMB + tid]; sL[i][tid] = 0.f; }
    __syncthreads();
    chol64(sA, sL, tid);
    for (int r = 0; r < EMB; r++)
        g_Lraw[(size_t)k * EMB * EMB + r * EMB + tid] = sL[r][tid];
}

// ---------------- 3xTF32 tensor-core GEMM -----------------------------------
// C[M,N] = act(A[M,Kd] @ W[N,Kd]^T + bias).  Block 128x64, warp 32x32 (4x2 warps).
template <int ACT>
__global__ __launch_bounds__(256) void mma_gemm(const float* __restrict__ A,
                                                const float* __restrict__ W,
                                                const float* __restrict__ bias,
                                                float* __restrict__ C,
                                                int M, int N, int Kd) {
    __shared__ float As[2][128][20];
    __shared__ float Ws[2][64][20];
    const int tid = threadIdx.x;
    const int lane = tid & 31, w = tid >> 5;
    const int gid = lane >> 2, tig = lane & 3;
    const int wm = w >> 1, wn = w & 1;
    const int m0 = blockIdx.y * 128, n0 = blockIdx.x * 64;

    float acc[2][4][4];
#pragma unroll
    for (int i = 0; i < 2; i++)
#pragma unroll
        for (int j = 0; j < 4; j++)
#pragma unroll
            for (int q = 0; q < 4; q++) acc[i][j][q] = 0.f;

    auto load_stage = [&](int s, int k0) {
#pragma unroll
        for (int q = 0; q < 2; q++) {
            int f = tid + q * 256;
            int r = f >> 2, c = (f & 3) * 4;
            cpa16(&As[s][r][c], A + (size_t)(m0 + r) * Kd + k0 + c);
        }
        {
            int r = tid >> 2, c = (tid & 3) * 4;
            cpa16(&Ws[s][r][c], W + (size_t)(n0 + r) * Kd + k0 + c);
        }
    };

    const int nst = Kd / 16;
    load_stage(0, 0); cp_commit();
    for (int s = 0; s < nst; s++) {
        if (s + 1 < nst) { load_stage((s + 1) & 1, (s + 1) * 16); cp_commit(); cp_wait<1>(); }
        else cp_wait<0>();
        __syncthreads();
        const int bs = s & 1;
#pragma unroll
        for (int kk = 0; kk < 16; kk += 8) {
            uint32_t ah[2][4], al[2][4], bh[4][2], bl[4][2];
#pragma unroll
            for (int mi = 0; mi < 2; mi++) {
                const int rb = wm * 32 + mi * 16;
                float a0 = As[bs][rb + gid][kk + tig];
                float a1 = As[bs][rb + gid + 8][kk + tig];
                float a2 = As[bs][rb + gid][kk + tig + 4];
                float a3 = As[bs][rb + gid + 8][kk + tig + 4];
                split_tf32(a0, ah[mi][0], al[mi][0]);
                split_tf32(a1, ah[mi][1], al[mi][1]);
                split_tf32(a2, ah[mi][2], al[mi][2]);
                split_tf32(a3, ah[mi][3], al[mi][3]);
            }
#pragma unroll
            for (int ni = 0; ni < 4; ni++) {
                const int nb = wn * 32 + ni * 8 + gid;
                float b0 = Ws[bs][nb][kk + tig];
                float b1 = Ws[bs][nb][kk + tig + 4];
                split_tf32(b0, bh[ni][0], bl[ni][0]);
                split_tf32(b1, bh[ni][1], bl[ni][1]);
            }
#pragma unroll
            for (int mi = 0; mi < 2; mi++)
#pragma unroll
                for (int ni = 0; ni < 4; ni++) {
                    mma8(acc[mi][ni], ah[mi], bl[ni]);
                    mma8(acc[mi][ni], al[mi], bh[ni]);
                    mma8(acc[mi][ni], ah[mi], bh[ni]);
                }
        }
        __syncthreads();
    }

#pragma unroll
    for (int mi = 0; mi < 2; mi++)
#pragma unroll
        for (int ni = 0; ni < 4; ni++) {
            const int row = m0 + wm * 32 + mi * 16 + gid;
            const int col = n0 + wn * 32 + ni * 8 + 2 * tig;
            const float bv0 = __ldg(bias + col), bv1 = __ldg(bias + col + 1);
            float v0 = acc[mi][ni][0] + bv0, v1 = acc[mi][ni][1] + bv1;
            float v2 = acc[mi][ni][2] + bv0, v3 = acc[mi][ni][3] + bv1;
            if (ACT) { v0 = selu_f(v0); v1 = selu_f(v1); v2 = selu_f(v2); v3 = selu_f(v3); }
            *reinterpret_cast<float2*>(C + (size_t)row * N + col) = make_float2(v0, v1);
            *reinterpret_cast<float2*>(C + (size_t)(row + 8) * N + col) = make_float2(v2, v3);
        }
}

// ---------------- fused quad/log_prob kernel --------------------------------
// Each block owns 2 clusters (M_k resident in smem) and streams all enc rows.
// lpT[k][b] = c_k - 0.5 * |M_k enc_b - t_k|^2   (3xTF32 mma)
__global__ __launch_bounds__(256) void quad_kernel() {
    __shared__ float Ms[128][68];   // [2*64 n][64 k]
    __shared__ float Ts[128];
    __shared__ float Es[2][64][20];
    __shared__ float sP[64][4];
    const int tid = threadIdx.x;
    const int lane = tid & 31, w = tid >> 5;
    const int gid = lane >> 2, tig = lane & 3;
    const int wm = w & 1, wn = w >> 1;        // 2 m-warps x 4 n-warps
    const int kc0 = blockIdx.x * 2;

    for (int f = tid; f < 2048; f += 256) {
        int r = f >> 4, c = (f & 15) * 4;
        *reinterpret_cast<float4*>(&Ms[r][c]) =
            *reinterpret_cast<const float4*>(g_M + (size_t)kc0 * 4096 + r * 64 + c);
    }
    if (tid < 128) Ts[tid] = g_t[kc0 * 64 + tid];
    __syncthreads();
    const float cK0 = g_c[kc0], cK1 = g_c[kc0 + 1];

    for (int tile = 0; tile < BATCH / 64; tile++) {
        const int b0 = tile * 64;
        float acc[2][4][4];
#pragma unroll
        for (int i = 0; i < 2; i++)
#pragma unroll
            for (int j = 0; j < 4; j++)
#pragma unroll
                for (int q = 0; q < 4; q++) acc[i][j][q] = 0.f;

        auto loadE = [&](int s, int k0) {
            int r = tid >> 2, c = (tid & 3) * 4;
            cpa16(&Es[s][r][c], g_enc + (size_t)(b0 + r) * 64 + k0 + c);
        };
        loadE(0, 0); cp_commit();
        for (int s = 0; s < 4; s++) {
            if (s < 3) { loadE((s + 1) & 1, (s + 1) * 16); cp_commit(); cp_wait<1>(); }
            else cp_wait<0>();
            __syncthreads();
            const int bs = s & 1;
#pragma unroll
            for (int kk = 0; kk < 16; kk += 8) {
                uint32_t ah[2][4], al[2][4], bh[4][2], bl[4][2];
#pragma unroll
                for (int mi = 0; mi < 2; mi++) {
                    const int rb = wm * 32 + mi * 16;
                    float a0 = Es[bs][rb + gid][kk + tig];
                    float a1 = Es[bs][rb + gid + 8][kk + tig];
                    float a2 = Es[bs][rb + gid][kk + tig + 4];
                    float a3 = Es[bs][rb + gid + 8][kk + tig + 4];
                    split_tf32(a0, ah[mi][0], al[mi][0]);
                    split_tf32(a1, ah[mi][1], al[mi][1]);
                    split_tf32(a2, ah[mi][2], al[mi][2]);
                    split_tf32(a3, ah[mi][3], al[mi][3]);
                }
                const int kg = s * 16 + kk;
#pragma unroll
                for (int ni = 0; ni < 4; ni++) {
                    const int nb = wn * 32 + ni * 8 + gid;
                    float b0f = Ms[nb][kg + tig];
                    float b1f = Ms[nb][kg + tig + 4];
                    split_tf32(b0f, bh[ni][0], bl[ni][0]);
                    split_tf32(b1f, bh[ni][1], bl[ni][1]);
                }
#pragma unroll
                for (int mi = 0; mi < 2; mi++)
#pragma unroll
                    for (int ni = 0; ni < 4; ni++) {
                        mma8(acc[mi][ni], ah[mi], bl[ni]);
                        mma8(acc[mi][ni], al[mi], bh[ni]);
                        mma8(acc[mi][ni], ah[mi], bh[ni]);
                    }
            }
            __syncthreads();
        }
        // epilogue: quad = sum over 64 cols of (z - t)^2
#pragma unroll
        for (int mi = 0; mi < 2; mi++)
#pragma unroll
            for (int h = 0; h < 2; h++) {
                float q = 0.f;
#pragma unroll
                for (int ni = 0; ni < 4; ni++) {
                    const int col = wn * 32 + ni * 8 + 2 * tig;
                    float z0 = acc[mi][ni][2 * h] - Ts[col];
                    float z1 = acc[mi][ni][2 * h + 1] - Ts[col + 1];
                    q = fmaf(z0, z0, fmaf(z1, z1, q));
                }
                q += __shfl_xor_sync(0xffffffffu, q, 1);
                q += __shfl_xor_sync(0xffffffffu, q, 2);
                if (tig == 0) sP[wm * 32 + mi * 16 + gid + 8 * h][wn] = q;
            }
        __syncthreads();
        if (tid < 128) {
            const int row = tid & 63, c = tid >> 6;
            float quad = sP[row][2 * c] + sP[row][2 * c + 1];
            float lp = (c ? cK1 : cK0) - 0.5f * quad;
            g_lpT[(size_t)(kc0 + c) * BATCH + b0 + row] = lp;
        }
        __syncthreads();
    }
}

// ---------------- transpose lpT -> out_lp [B][K] ----------------------------
__global__ void transpose_lp(float* __restrict__ out_lp) {
    __shared__ float t[32][33];
    const int bx = blockIdx.x * 32, ky = blockIdx.y * 32;
    const int tx = threadIdx.x, ty = threadIdx.y;  // (32, 8)
#pragma unroll
    for (int i = 0; i < 4; i++)
        t[ty + 8 * i][tx] = g_lpT[(size_t)(ky + ty + 8 * i) * BATCH + bx + tx];
    __syncthreads();
#pragma unroll
    for (int i = 0; i < 4; i++)
        out_lp[(size_t)(bx + ty + 8 * i) * KC + ky + tx] = t[tx][ty + 8 * i];
}

// ---------------- argmax over K per row (first-max tie semantics) -----------
__global__ void argmax_kernel(const float* __restrict__ lp, float* __restrict__ out_idx) {
    const int row = blockIdx.x * 8 + (threadIdx.x >> 5);
    const int lane = threadIdx.x & 31;
    float best = -3.4e38f; int bi = 0;
#pragma unroll
    for (int q = 0; q < 2; q++) {
        const int k = lane * 4 + q * 128;
        float4 v = *reinterpret_cast<const float4*>(lp + (size_t)row * KC + k);
        if (v.x > best) { best = v.x; bi = k; }
        if (v.y > best) { best = v.y; bi = k + 1; }
        if (v.z > best) { best = v.z; bi = k + 2; }
        if (v.w > best) { best = v.w; bi = k + 3; }
    }
#pragma unroll
    for (int o = 16; o; o >>= 1) {
        float ov = __shfl_xor_sync(0xffffffffu, best, o);
        int oi = __shfl_xor_sync(0xffffffffu, bi, o);
        if (ov > best || (ov == best && oi < bi)) { best = ov; bi = oi; }
    }
    if (lane == 0) { g_idx[row] = bi; out_idx[row] = (float)bi; }
}

// ---------------- sample = means[idx] + L_raw[idx] @ noise ------------------
__global__ void sample_kernel(const float* __restrict__ means,
                              const float* __restrict__ noise) {
    __shared__ float sn[EMB];
    const int bb = blockIdx.x;
    const int i = threadIdx.x;
    sn[i] = noise[(size_t)bb * EMB + i];
    __syncthreads();
    const int k = g_idx[bb];
    const float* Lr = g_Lraw + (size_t)k * EMB * EMB + i * EMB;
    float s = means[k * EMB + i];
    for (int j = 0; j <= i; j++) s = fmaf(Lr[j], sn[j], s);
    g_sample[(size_t)bb * EMB + i] = s;
}

// ---------------- launch ----------------------------------------------------
extern "C" void kernel_launch(void* const* d_in, const int* in_sizes, int n_in,
                              void* d_out, int out_size) {
    const float* x     = (const float*)d_in[0];
    const float* noise = (const float*)d_in[1];
    const float* eW1 = (const float*)d_in[2];  const float* eb1 = (const float*)d_in[3];
    const float* eW2 = (const float*)d_in[4];  const float* eb2 = (const float*)d_in[5];
    const float* eW3 = (const float*)d_in[6];  const float* eb3 = (const float*)d_in[7];
    const float* dW1 = (const float*)d_in[8];  const float* db1 = (const float*)d_in[9];
    const float* dW2 = (const float*)d_in[10]; const float* db2 = (const float*)d_in[11];
    const float* dW3 = (const float*)d_in[12]; const float* db3 = (const float*)d_in[13];
    const float* means = (const float*)d_in[14];
    const float* sizes = (const float*)d_in[15];
    const float* cov   = (const float*)d_in[16];

    float* out = (float*)d_out;
    float* out_dec = out;
    float* out_lp  = out + (size_t)BATCH * INDIM;
    float* out_idx = out + (size_t)BATCH * (INDIM + KC);

    float *h1, *h2, *enc, *smp;
    cudaGetSymbolAddress((void**)&h1, g_h1);
    cudaGetSymbolAddress((void**)&h2, g_h2);
    cudaGetSymbolAddress((void**)&enc, g_enc);
    cudaGetSymbolAddress((void**)&smp, g_sample);

    prep_clusters<<<KC, EMB>>>(cov, means, sizes);

    // encoder
    mma_gemm<1><<<dim3(DENSE / 64, BATCH / 128), 256>>>(x,  eW1, eb1, h1, BATCH, DENSE, INDIM);
    mma_gemm<1><<<dim3(DENSE / 64, BATCH / 128), 256>>>(h1, eW2, eb2, h2, BATCH, DENSE, DENSE);
    mma_gemm<0><<<dim3(EMB / 64, BATCH / 128), 256>>>(h2, eW3, eb3, enc, BATCH, EMB, DENSE);

    // quantize
    quad_kernel<<<KC / 2, 256>>>();
    transpose_lp<<<dim3(BATCH / 32, KC / 32), dim3(32, 8)>>>(out_lp);
    argmax_kernel<<<BATCH / 8, 256>>>(out_lp, out_idx);
    sample_kernel<<<BATCH, EMB>>>(means, noise);

    // decoder
    mma_gemm<1><<<dim3(DENSE / 64, BATCH / 128), 256>>>(smp, dW1, db1, h1, BATCH, DENSE, EMB);
    mma_gemm<1><<<dim3(DENSE / 64, BATCH / 128), 256>>>(h1,  dW2, db2, h2, BATCH, DENSE, DENSE);
    mma_gemm<0><<<dim3(INDIM / 64, BATCH / 128), 256>>>(h2, dW3, db3, out_dec, BATCH, INDIM, DENSE);
}